// round 10
// baseline (speedup 1.0000x reference)
#include <cuda_runtime.h>
#include <cuda_bf16.h>
#include <cuda_fp16.h>
#include <cstdint>

// Problem constants
#define HH   64
#define WW   128
#define CC   256
#define NPIX (HH * WW)          // 8192
#define NH   8
#define HD   32
#define C3   (3 * CC)           // 768
#define KK   7

// ---------------------------------------------------------------------------
// Scratch (device globals; no allocation allowed)
// ---------------------------------------------------------------------------
__device__ __align__(16) float         g_q[NPIX * CC];          // q fp32
__device__ __align__(16) __half        g_kv[NPIX * 2 * CC];     // k|v fp16 (512/pix)
__device__ __align__(16) __nv_bfloat16 g_xh[NPIX * CC];
__device__ __align__(16) __nv_bfloat16 g_xl[NPIX * CC];
__device__ __align__(16) __nv_bfloat16 g_wqkvT_h[C3 * CC];
__device__ __align__(16) __nv_bfloat16 g_wqkvT_l[C3 * CC];
__device__ __align__(16) __nv_bfloat16 g_wprojT_h[CC * CC];
__device__ __align__(16) __nv_bfloat16 g_wprojT_l[CC * CC];
__device__ __align__(16) __nv_bfloat16 g_atth[NPIX * CC];
__device__ __align__(16) __nv_bfloat16 g_attl[NPIX * CC];

// 8-byte pair of half2 (4 fp16 values) for vectorized smem access
struct __align__(8) h2x2 { __half2 a, b; };

// ---------------------------------------------------------------------------
// PTX helpers (baseline ISA: mma.sync / ldmatrix / cp.async)
// ---------------------------------------------------------------------------
__device__ __forceinline__ uint32_t smem_u32(const void* p) {
    uint32_t a;
    asm("{ .reg .u64 t; cvta.to.shared.u64 t, %1; cvt.u32.u64 %0, t; }"
        : "=r"(a) : "l"(p));
    return a;
}

__device__ __forceinline__ void cp_async16(uint32_t saddr, const void* gptr) {
    asm volatile("cp.async.cg.shared.global [%0], [%1], 16;"
                 :: "r"(saddr), "l"(gptr) : "memory");
}

__device__ __forceinline__ void ldsm_x4(uint32_t* r, uint32_t addr) {
    asm volatile("ldmatrix.sync.aligned.m8n8.x4.shared.b16 {%0,%1,%2,%3}, [%4];"
                 : "=r"(r[0]), "=r"(r[1]), "=r"(r[2]), "=r"(r[3]) : "r"(addr));
}

__device__ __forceinline__ void mma_16816(float* c, const uint32_t* a,
                                          const uint32_t* b) {
    asm volatile(
        "mma.sync.aligned.m16n8k16.row.col.f32.bf16.bf16.f32 "
        "{%0,%1,%2,%3}, {%4,%5,%6,%7}, {%8,%9}, {%0,%1,%2,%3};"
        : "+f"(c[0]), "+f"(c[1]), "+f"(c[2]), "+f"(c[3])
        : "r"(a[0]), "r"(a[1]), "r"(a[2]), "r"(a[3]), "r"(b[0]), "r"(b[1]));
}

// ---------------------------------------------------------------------------
// Fused prep: split x (hi/lo bf16, float4-vectorized) + transpose/split weights
// ---------------------------------------------------------------------------
#define PREP_XB  (NPIX * CC / 1024)           // 2048 (4 elems/thread)
#define PREP_QB  (CC * C3 / 256)              // 768
#define PREP_PB  (CC * CC / 256)              // 256

__global__ void prep_all(const float* __restrict__ x,
                         const float* __restrict__ wq,
                         const float* __restrict__ wp,
                         __nv_bfloat16* __restrict__ xh, __nv_bfloat16* __restrict__ xl,
                         __nv_bfloat16* __restrict__ qh, __nv_bfloat16* __restrict__ ql,
                         __nv_bfloat16* __restrict__ ph, __nv_bfloat16* __restrict__ pl)
{
    const int b = blockIdx.x;
    if (b < PREP_XB) {
        const int i4 = (b * 256 + threadIdx.x) * 4;
        const float4 v = *(const float4*)&x[i4];
        __nv_bfloat16 h[4], l[4];
        const float vv[4] = {v.x, v.y, v.z, v.w};
#pragma unroll
        for (int j = 0; j < 4; j++) {
            h[j] = __float2bfloat16(vv[j]);
            l[j] = __float2bfloat16(vv[j] - __bfloat162float(h[j]));
        }
        *(uint2*)&xh[i4] = *(const uint2*)h;
        *(uint2*)&xl[i4] = *(const uint2*)l;
    } else if (b < PREP_XB + PREP_QB) {
        const int i = (b - PREP_XB) * 256 + threadIdx.x;   // over C3*CC
        const int n = i / CC, k = i % CC;
        const float v = wq[(size_t)k * C3 + n];
        const __nv_bfloat16 hi = __float2bfloat16(v);
        qh[i] = hi;                                        // i == n*CC + k
        ql[i] = __float2bfloat16(v - __bfloat162float(hi));
    } else {
        const int i = (b - PREP_XB - PREP_QB) * 256 + threadIdx.x;  // CC*CC
        const int n = i / CC, k = i % CC;
        const float v = wp[(size_t)k * CC + n];
        const __nv_bfloat16 hi = __float2bfloat16(v);
        ph[i] = hi;
        pl[i] = __float2bfloat16(v - __bfloat162float(hi));
    }
}

// ---------------------------------------------------------------------------
// mma.sync bf16-split GEMM: C = (Ah+Al)[M,K] @ (Bh+Bl)[N,K]^T + bias
// 3-term: Ah@Bh + Ah@Bl + Al@Bh. CTA tile 128x128, 4 warps (2M x 2N),
// warp tile 64x64 (85 B smem per MMA -> crossbar ceiling ~75%).
// K chunks of 32, 2-stage cp.async. Rows padded to 80B (stride-5 banks,
// conflict-free ldmatrix without swizzle).
// Output: tiles bx < nq write fp32 (width 256); tiles bx >= nq write fp16
// into the kv buffer (width 512 halves), for direct attention consumption.
// ---------------------------------------------------------------------------
#define BKC   32
#define ROWB  80                              // 64B data + 16B pad
#define ABUF  (128 * ROWB)                    // 10240 per buffer
#define STG_BYTES (4 * ABUF)                  // 40960 (Ah|Al|Bh|Bl)
#define GT_SMEM (2 * STG_BYTES)               // 81920

__global__ __launch_bounds__(128, 2)
void gemm_mma(const __nv_bfloat16* __restrict__ Ah, const __nv_bfloat16* __restrict__ Al,
              const __nv_bfloat16* __restrict__ Bh, const __nv_bfloat16* __restrict__ Bl,
              const float* __restrict__ bias,
              float* __restrict__ Cq, __half* __restrict__ Ckv,
              int nq, int K)
{
    extern __shared__ char smem[];
    const uint32_t sb = smem_u32(smem);
    const int tid  = threadIdx.x;
    const int wid  = tid >> 5;
    const int lane = tid & 31;
    const int warpM = wid & 1;               // 0..1  (64 rows each)
    const int warpN = wid >> 1;              // 0..1  (64 cols each)

    const size_t aBase = (size_t)blockIdx.y * 128 * K;
    const size_t bBase = (size_t)blockIdx.x * 128 * K;
    const int nch = K / BKC;

    auto issue_chunk = [&](int c) {
        const uint32_t st = sb + (uint32_t)(c & 1) * STG_BYTES;
        const int k0 = c * BKC;
        // each matrix: 128 rows x 4 16B-units = 512 transfers -> 4 iters
#pragma unroll
        for (int i = 0; i < 4; i++) {
            const int idx = i * 128 + tid;
            const int r = idx >> 2, u = idx & 3;
            const uint32_t so = (uint32_t)r * ROWB + (uint32_t)u * 16;
            const size_t ga = aBase + (size_t)r * K + k0 + u * 8;
            const size_t gb = bBase + (size_t)r * K + k0 + u * 8;
            cp_async16(st + so,            Ah + ga);
            cp_async16(st + ABUF + so,     Al + ga);
            cp_async16(st + 2 * ABUF + so, Bh + gb);
            cp_async16(st + 3 * ABUF + so, Bl + gb);
        }
        asm volatile("cp.async.commit_group;" ::: "memory");
    };

    float acc[4][8][4];
#pragma unroll
    for (int i = 0; i < 4; i++)
#pragma unroll
        for (int j = 0; j < 8; j++)
#pragma unroll
            for (int t = 0; t < 4; t++) acc[i][j][t] = 0.0f;

    // ldmatrix lane address components
    const uint32_t arow  = (uint32_t)(warpM * 64 + (lane & 15));
    const uint32_t acolL = (uint32_t)((lane >> 4) * 16);
    const uint32_t brow  = (uint32_t)(warpN * 64 + (lane & 7) + ((lane >> 4) << 3));
    const uint32_t bcolL = (uint32_t)(((lane >> 3) & 1) * 16);

    issue_chunk(0);

    for (int c = 0; c < nch; c++) {
        if (c + 1 < nch) {
            issue_chunk(c + 1);
            asm volatile("cp.async.wait_group 1;" ::: "memory");
        } else {
            asm volatile("cp.async.wait_group 0;" ::: "memory");
        }
        __syncthreads();

        const uint32_t st  = sb + (uint32_t)(c & 1) * STG_BYTES;
        const uint32_t sA0 = st;
        const uint32_t sA1 = st + ABUF;
        const uint32_t sB0 = st + 2 * ABUF;
        const uint32_t sB1 = st + 3 * ABUF;

#pragma unroll
        for (int ks = 0; ks < 2; ks++) {
            const uint32_t kb = (uint32_t)ks * 32;

            uint32_t ah[4][4], al[4][4];
#pragma unroll
            for (int ma = 0; ma < 4; ma++) {
                const uint32_t off = (arow + ma * 16) * ROWB + kb + acolL;
                ldsm_x4(ah[ma], sA0 + off);
                ldsm_x4(al[ma], sA1 + off);
            }

            uint32_t bh[8][2], bl[8][2];
#pragma unroll
            for (int g = 0; g < 4; g++) {
                const uint32_t off = (brow + g * 16) * ROWB + kb + bcolL;
                uint32_t t0[4], t1[4];
                ldsm_x4(t0, sB0 + off);
                ldsm_x4(t1, sB1 + off);
                bh[2 * g][0] = t0[0]; bh[2 * g][1] = t0[1];
                bh[2 * g + 1][0] = t0[2]; bh[2 * g + 1][1] = t0[3];
                bl[2 * g][0] = t1[0]; bl[2 * g][1] = t1[1];
                bl[2 * g + 1][0] = t1[2]; bl[2 * g + 1][1] = t1[3];
            }

#pragma unroll
            for (int ma = 0; ma < 4; ma++)
#pragma unroll
                for (int na = 0; na < 8; na++) {
                    mma_16816(acc[ma][na], ah[ma], bh[na]);
                    mma_16816(acc[ma][na], ah[ma], bl[na]);
                    mma_16816(acc[ma][na], al[ma], bh[na]);
                }
        }
        __syncthreads();
    }

    // ---- epilogue ----
    const int bx = blockIdx.x;
    const int row0 = blockIdx.y * 128 + warpM * 64 + (lane >> 2);
    const int wcol0 = warpN * 64 + (lane & 3) * 2;     // col within CTA tile
#pragma unroll
    for (int na = 0; na < 8; na++) {
        const int wc = wcol0 + na * 8;
        const int gcol = bx * 128 + wc;                // col in full N (bias)
        const float2 b2 = *(const float2*)&bias[gcol];
        if (bx < nq) {
            // fp32 output, width 256
#pragma unroll
            for (int ma = 0; ma < 4; ma++) {
                const int r = row0 + ma * 16;
                float2 o0, o1;
                o0.x = acc[ma][na][0] + b2.x;
                o0.y = acc[ma][na][1] + b2.y;
                o1.x = acc[ma][na][2] + b2.x;
                o1.y = acc[ma][na][3] + b2.y;
                *(float2*)&Cq[(size_t)r * 256 + gcol]       = o0;
                *(float2*)&Cq[(size_t)(r + 8) * 256 + gcol] = o1;
            }
        } else {
            // fp16 output into kv buffer, width 512 halves
            const int kvc = (bx - nq) * 128 + wc;
#pragma unroll
            for (int ma = 0; ma < 4; ma++) {
                const int r = row0 + ma * 16;
                __half2 o0 = __floats2half2_rn(acc[ma][na][0] + b2.x,
                                               acc[ma][na][1] + b2.y);
                __half2 o1 = __floats2half2_rn(acc[ma][na][2] + b2.x,
                                               acc[ma][na][3] + b2.y);
                *(__half2*)&Ckv[(size_t)r * 512 + kvc]       = o0;
                *(__half2*)&Ckv[(size_t)(r + 8) * 512 + kvc] = o1;
            }
        }
    }
}

// ---------------------------------------------------------------------------
// 2D neighborhood attention (7x7), one block = 8x8 pixel tile x 1 head.
// q from fp32 buffer; k/v already fp16 in g_kv -> straight uint2 copy to smem.
// 8 lanes per pixel (lane owns 4 dims). Transpose-reduce scores; exp once
// per neighbor; width-8 shfl rebroadcast in pass 2.
// ---------------------------------------------------------------------------
__global__ __launch_bounds__(256, 1)
void na_attn(const float* __restrict__ qbuf, const __half* __restrict__ kvbuf,
             __nv_bfloat16* __restrict__ outh, __nv_bfloat16* __restrict__ outl)
{
    extern __shared__ h2x2 smn[];

    const int c0   = blockIdx.x * 8;
    const int r0   = blockIdx.y * 8;
    const int head = blockIdx.z;

    const int rlo = max(r0 - 3, 0);
    const int rhi = min(r0 + 10, HH - 1);
    const int nr  = rhi - rlo + 1;
    const int clo = max(c0 - 3, 0);
    const int chi = min(c0 + 10, WW - 1);
    const int nc  = chi - clo + 1;
    const int npx = nr * nc;

    h2x2* sK = smn;                    // npx * 8 h2x2 (32 halves per pixel)
    h2x2* sV = smn + npx * 8;

    const int tid = threadIdx.x;

    // Straight copy of fp16 k/v window into smem (no conversion)
    for (int t = tid; t < npx * (HD / 4); t += 256) {
        int p = t >> 3;
        int f = t & 7;
        int gy = rlo + p / nc;
        int gx = clo + p % nc;
        const __half* base = kvbuf + (size_t)(gy * WW + gx) * 512 + head * HD;
        sK[p * 8 + f] = *(const h2x2*)(base + f * 4);
        sV[p * 8 + f] = *(const h2x2*)(base + 256 + f * 4);
    }
    __syncthreads();

    const int warp = tid >> 5;
    const int lane = tid & 31;
    const int sub  = lane >> 3;
    const int l8   = lane & 7;
    const int gy   = r0 + warp;
    const float scale = 0.17677669529663687f;   // 1/sqrt(32)

    const int sy = min(max(gy - 3, 0), HH - KK) - rlo;

#pragma unroll
    for (int t = 0; t < 2; t++) {
        const int gx = c0 + t * 4 + sub;
        const size_t pix = (size_t)(gy * WW + gx);

        float4 q4 = *(const float4*)&qbuf[pix * CC + head * HD + l8 * 4];
        q4.x *= scale; q4.y *= scale; q4.z *= scale; q4.w *= scale;

        const int sx = min(max(gx - 3, 0), WW - KK) - clo;
        const int base = (sy * nc + sx) * 8 + l8;   // h2x2 index

        // ---- pass 1: scores. 6 groups of 8 + neighbor 48 ----
        float own[6];      // lane owns score of neighbor g*8 + l8
#pragma unroll
        for (int g = 0; g < 6; g++) {
            float r[8];
#pragma unroll
            for (int j = 0; j < 8; j++) {
                const int idx = g * 8 + j;
                const int p = idx / KK, q = idx % KK;
                const h2x2 kp = sK[base + (p * nc + q) * 8];
                const float2 k01 = __half22float2(kp.a);
                const float2 k23 = __half22float2(kp.b);
                float s = q4.x * k01.x;
                s = fmaf(q4.y, k01.y, s);
                s = fmaf(q4.z, k23.x, s);
                s = fmaf(q4.w, k23.y, s);
                r[j] = s;
            }
            // 8x8 transpose-reduce: 7 shfl; lane l8 ends with neighbor g*8+l8
#pragma unroll
            for (int j = 0; j < 4; j++) {
                float snd = (l8 & 4) ? r[j] : r[j + 4];
                float rcv = __shfl_xor_sync(0xffffffffu, snd, 4);
                r[j] = ((l8 & 4) ? r[j + 4] : r[j]) + rcv;
            }
#pragma unroll
            for (int j = 0; j < 2; j++) {
                float snd = (l8 & 2) ? r[j] : r[j + 2];
                float rcv = __shfl_xor_sync(0xffffffffu, snd, 2);
                r[j] = ((l8 & 2) ? r[j + 2] : r[j]) + rcv;
            }
            {
                float snd = (l8 & 1) ? r[0] : r[1];
                float rcv = __shfl_xor_sync(0xffffffffu, snd, 1);
                r[0] = ((l8 & 1) ? r[1] : r[0]) + rcv;
            }
            own[g] = r[0];
        }
        // neighbor 48 (p=6,q=6): classic butterfly, all lanes get it
        float s48;
        {
            const h2x2 kp = sK[base + (6 * nc + 6) * 8];
            const float2 k01 = __half22float2(kp.a);
            const float2 k23 = __half22float2(kp.b);
            float s = q4.x * k01.x;
            s = fmaf(q4.y, k01.y, s);
            s = fmaf(q4.z, k23.x, s);
            s = fmaf(q4.w, k23.y, s);
            s += __shfl_xor_sync(0xffffffffu, s, 4);
            s += __shfl_xor_sync(0xffffffffu, s, 2);
            s += __shfl_xor_sync(0xffffffffu, s, 1);
            s48 = s;
        }

        // ---- max (distributed + butterfly) ----
        float m = s48;
#pragma unroll
        for (int g = 0; g < 6; g++) m = fmaxf(m, own[g]);
        m = fmaxf(m, __shfl_xor_sync(0xffffffffu, m, 4));
        m = fmaxf(m, __shfl_xor_sync(0xffffffffu, m, 2));
        m = fmaxf(m, __shfl_xor_sync(0xffffffffu, m, 1));

        // ---- exp (once per neighbor) + sum ----
        float e[6];
        float esum = 0.0f;
#pragma unroll
        for (int g = 0; g < 6; g++) {
            e[g] = __expf(own[g] - m);
            esum += e[g];
        }
        esum += __shfl_xor_sync(0xffffffffu, esum, 4);
        esum += __shfl_xor_sync(0xffffffffu, esum, 2);
        esum += __shfl_xor_sync(0xffffffffu, esum, 1);
        const float e48 = __expf(s48 - m);
        const float l = esum + e48;

        // ---- pass 2: weighted V accumulation ----
        float4 acc = make_float4(0.f, 0.f, 0.f, 0.f);
#pragma unroll
        for (int g = 0; g < 6; g++) {
#pragma unroll
            for (int j = 0; j < 8; j++) {
                const float eb = __shfl_sync(0xffffffffu, e[g], j, 8);
                const int idx = g * 8 + j;
                const int p = idx / KK, q = idx % KK;
                const h2x2 vp = sV[base + (p * nc + q) * 8];
                const float2 v01 = __half22float2(vp.a);
                const float2 v23 = __half22float2(vp.b);
                acc.x = fmaf(eb, v01.x, acc.x);
                acc.y = fmaf(eb, v01.y, acc.y);
                acc.z = fmaf(eb, v23.x, acc.z);
                acc.w = fmaf(eb, v23.y, acc.w);
            }
        }
        {
            const h2x2 vp = sV[base + (6 * nc + 6) * 8];
            const float2 v01 = __half22float2(vp.a);
            const float2 v23 = __half22float2(vp.b);
            acc.x = fmaf(e48, v01.x, acc.x);
            acc.y = fmaf(e48, v01.y, acc.y);
            acc.z = fmaf(e48, v23.x, acc.z);
            acc.w = fmaf(e48, v23.y, acc.w);
        }

        const float inv = 1.0f / l;
        float vals[4] = {acc.x * inv, acc.y * inv, acc.z * inv, acc.w * inv};
        const size_t idx = pix * CC + head * HD + l8 * 4;
#pragma unroll
        for (int j = 0; j < 4; j++) {
            __nv_bfloat16 hi = __float2bfloat16(vals[j]);
            outh[idx + j] = hi;
            outl[idx + j] = __float2bfloat16(vals[j] - __bfloat162float(hi));
        }
    }
}

// ---------------------------------------------------------------------------
// kernel_launch
// ---------------------------------------------------------------------------
extern "C" void kernel_launch(void* const* d_in, const int* in_sizes, int n_in,
                              void* d_out, int out_size)
{
    const float* x      = (const float*)d_in[0];
    const float* w_qkv  = (const float*)d_in[1];
    const float* b_qkv  = (const float*)d_in[2];
    const float* w_proj = (const float*)d_in[3];
    const float* b_proj = (const float*)d_in[4];
    float* out = (float*)d_out;

    float *qb;
    __half *kvb;
    __nv_bfloat16 *xh, *xl, *wqh, *wql, *wph, *wpl, *ath, *atl;
    cudaGetSymbolAddress((void**)&qb,  g_q);
    cudaGetSymbolAddress((void**)&kvb, g_kv);
    cudaGetSymbolAddress((void**)&xh,  g_xh);
    cudaGetSymbolAddress((void**)&xl,  g_xl);
    cudaGetSymbolAddress((void**)&wqh, g_wqkvT_h);
    cudaGetSymbolAddress((void**)&wql, g_wqkvT_l);
    cudaGetSymbolAddress((void**)&wph, g_wprojT_h);
    cudaGetSymbolAddress((void**)&wpl, g_wprojT_l);
    cudaGetSymbolAddress((void**)&ath, g_atth);
    cudaGetSymbolAddress((void**)&atl, g_attl);

    cudaFuncSetAttribute(gemm_mma, cudaFuncAttributeMaxDynamicSharedMemorySize,
                         GT_SMEM);

    // 0) Fused prep: split x (vectorized) + transpose/split both weights
    prep_all<<<PREP_XB + PREP_QB + PREP_PB, 256>>>(x, w_qkv, w_proj,
                                                   xh, xl, wqh, wql, wph, wpl);

    // 1) QKV projection: [8192,256] @ [256,768] + b
    //    tiles 0-1 -> q fp32; tiles 2-5 -> k|v fp16 into kv buffer
    {
        dim3 grid(C3 / 128, NPIX / 128);
        gemm_mma<<<grid, 128, GT_SMEM>>>(xh, xl, wqh, wql, b_qkv,
                                         qb, kvb, /*nq=*/2, CC);
    }

    // 2) Neighborhood attention (fp16 k/v direct; emits bf16 hi/lo)
    {
        const int smem = 2 * 14 * 14 * 8 * (int)sizeof(h2x2);  // 25088 B
        dim3 grid(WW / 8, HH / 8, NH);
        na_attn<<<grid, 256, smem>>>(qb, kvb, ath, atl);
    }

    // 3) Output projection: [8192,256] @ [256,256] + b (all fp32 tiles)
    {
        dim3 grid(CC / 128, NPIX / 128);
        gemm_mma<<<grid, 128, GT_SMEM>>>(ath, atl, wph, wpl, b_proj,
                                         out, (__half*)nullptr, /*nq=*/2, CC);
    }
}

// round 11
// speedup vs baseline: 1.0990x; 1.0990x over previous
#include <cuda_runtime.h>
#include <cuda_bf16.h>
#include <cuda_fp16.h>
#include <cstdint>

// Problem constants
#define HH   64
#define WW   128
#define CC   256
#define NPIX (HH * WW)          // 8192
#define NH   8
#define HD   32
#define C3   (3 * CC)           // 768
#define KK   7

// ---------------------------------------------------------------------------
// Scratch (device globals; no allocation allowed)
// ---------------------------------------------------------------------------
__device__ __align__(16) float         g_q[NPIX * CC];          // q fp32
__device__ __align__(16) __half        g_kv[NPIX * 2 * CC];     // k|v fp16 (512/pix)
__device__ __align__(16) __nv_bfloat16 g_xh[NPIX * CC];
__device__ __align__(16) __nv_bfloat16 g_xl[NPIX * CC];
__device__ __align__(16) __nv_bfloat16 g_wqkvT_h[C3 * CC];
__device__ __align__(16) __nv_bfloat16 g_wqkvT_l[C3 * CC];
__device__ __align__(16) __nv_bfloat16 g_wprojT_h[CC * CC];
__device__ __align__(16) __nv_bfloat16 g_wprojT_l[CC * CC];
__device__ __align__(16) __nv_bfloat16 g_atth[NPIX * CC];
__device__ __align__(16) __nv_bfloat16 g_attl[NPIX * CC];

// 8-byte pair of half2 (4 fp16 values) for vectorized smem access
struct __align__(8) h2x2 { __half2 a, b; };

// ---------------------------------------------------------------------------
// PTX helpers (baseline ISA: mma.sync / ldmatrix / cp.async)
// ---------------------------------------------------------------------------
__device__ __forceinline__ uint32_t smem_u32(const void* p) {
    uint32_t a;
    asm("{ .reg .u64 t; cvta.to.shared.u64 t, %1; cvt.u32.u64 %0, t; }"
        : "=r"(a) : "l"(p));
    return a;
}

__device__ __forceinline__ void cp_async16(uint32_t saddr, const void* gptr) {
    asm volatile("cp.async.cg.shared.global [%0], [%1], 16;"
                 :: "r"(saddr), "l"(gptr) : "memory");
}

__device__ __forceinline__ void ldsm_x4(uint32_t* r, uint32_t addr) {
    asm volatile("ldmatrix.sync.aligned.m8n8.x4.shared.b16 {%0,%1,%2,%3}, [%4];"
                 : "=r"(r[0]), "=r"(r[1]), "=r"(r[2]), "=r"(r[3]) : "r"(addr));
}

__device__ __forceinline__ void mma_16816(float* c, const uint32_t* a,
                                          const uint32_t* b) {
    asm volatile(
        "mma.sync.aligned.m16n8k16.row.col.f32.bf16.bf16.f32 "
        "{%0,%1,%2,%3}, {%4,%5,%6,%7}, {%8,%9}, {%0,%1,%2,%3};"
        : "+f"(c[0]), "+f"(c[1]), "+f"(c[2]), "+f"(c[3])
        : "r"(a[0]), "r"(a[1]), "r"(a[2]), "r"(a[3]), "r"(b[0]), "r"(b[1]));
}

// SW128 swizzle: chunk bits [4:6] ^= row bits [7:9] (conflict-free ldmatrix)
__device__ __forceinline__ uint32_t sw128(uint32_t off) {
    return off ^ ((off >> 3) & 0x70);
}

// ---------------------------------------------------------------------------
// Fused prep: split x (hi/lo bf16, float4-vectorized) + transpose/split weights
// ---------------------------------------------------------------------------
#define PREP_XB  (NPIX * CC / 1024)           // 2048 (4 elems/thread)
#define PREP_QB  (CC * C3 / 256)              // 768
#define PREP_PB  (CC * CC / 256)              // 256

__global__ void prep_all(const float* __restrict__ x,
                         const float* __restrict__ wq,
                         const float* __restrict__ wp,
                         __nv_bfloat16* __restrict__ xh, __nv_bfloat16* __restrict__ xl,
                         __nv_bfloat16* __restrict__ qh, __nv_bfloat16* __restrict__ ql,
                         __nv_bfloat16* __restrict__ ph, __nv_bfloat16* __restrict__ pl)
{
    const int b = blockIdx.x;
    if (b < PREP_XB) {
        const int i4 = (b * 256 + threadIdx.x) * 4;
        const float4 v = *(const float4*)&x[i4];
        __nv_bfloat16 h[4], l[4];
        const float vv[4] = {v.x, v.y, v.z, v.w};
#pragma unroll
        for (int j = 0; j < 4; j++) {
            h[j] = __float2bfloat16(vv[j]);
            l[j] = __float2bfloat16(vv[j] - __bfloat162float(h[j]));
        }
        *(uint2*)&xh[i4] = *(const uint2*)h;
        *(uint2*)&xl[i4] = *(const uint2*)l;
    } else if (b < PREP_XB + PREP_QB) {
        const int i = (b - PREP_XB) * 256 + threadIdx.x;   // over C3*CC
        const int n = i / CC, k = i % CC;
        const float v = wq[(size_t)k * C3 + n];
        const __nv_bfloat16 hi = __float2bfloat16(v);
        qh[i] = hi;                                        // i == n*CC + k
        ql[i] = __float2bfloat16(v - __bfloat162float(hi));
    } else {
        const int i = (b - PREP_XB - PREP_QB) * 256 + threadIdx.x;  // CC*CC
        const int n = i / CC, k = i % CC;
        const float v = wp[(size_t)k * CC + n];
        const __nv_bfloat16 hi = __float2bfloat16(v);
        ph[i] = hi;
        pl[i] = __float2bfloat16(v - __bfloat162float(hi));
    }
}

// ---------------------------------------------------------------------------
// mma.sync bf16-split GEMM (R9 winning config): CTA 128x64, 4 warps (2Mx2N),
// warp tile 64x32, K chunks of 64, 2-stage cp.async, SW128 smem.
// 3-term: Ah@Bh + Ah@Bl + Al@Bh.
// Epilogue: tiles bx < nq  -> fp32 into Cq  (width 256)
//           tiles bx >= nq -> fp16 into Ckv (width 512 halves; k|v packed)
// ---------------------------------------------------------------------------
#define BKC 64
#define AB_BYTES (128 * 128)                 // 16384 per A buffer
#define BB_BYTES (64 * 128)                  // 8192  per B buffer
#define STG_BYTES (2 * AB_BYTES + 2 * BB_BYTES)  // 49152
#define GT_SMEM (2 * STG_BYTES)              // 98304

__global__ __launch_bounds__(128, 2)
void gemm_mma(const __nv_bfloat16* __restrict__ Ah, const __nv_bfloat16* __restrict__ Al,
              const __nv_bfloat16* __restrict__ Bh, const __nv_bfloat16* __restrict__ Bl,
              const float* __restrict__ bias,
              float* __restrict__ Cq, __half* __restrict__ Ckv,
              int nq, int K)
{
    extern __shared__ char smem[];
    const uint32_t sb = smem_u32(smem);
    const int tid  = threadIdx.x;
    const int wid  = tid >> 5;
    const int lane = tid & 31;
    const int warpM = wid & 1;               // 0..1  (64 rows each)
    const int warpN = wid >> 1;              // 0..1  (32 cols each)

    const size_t aBase = (size_t)blockIdx.y * 128 * K;
    const size_t bBase = (size_t)blockIdx.x * 64 * K;
    const int nch = K / BKC;

    auto issue_chunk = [&](int c) {
        const uint32_t st = sb + (uint32_t)(c & 1) * STG_BYTES;
        const int k0 = c * BKC;
#pragma unroll
        for (int i = 0; i < 8; i++) {
            const int idx = i * 128 + tid;
            const int r = idx >> 3, ch = idx & 7;
            const uint32_t so = sw128((uint32_t)r * 128 + (uint32_t)ch * 16);
            const size_t ga = aBase + (size_t)r * K + k0 + ch * 8;
            cp_async16(st + so, Ah + ga);
            cp_async16(st + AB_BYTES + so, Al + ga);
        }
#pragma unroll
        for (int i = 0; i < 4; i++) {
            const int idx = i * 128 + tid;
            const int r = idx >> 3, ch = idx & 7;
            const uint32_t so = sw128((uint32_t)r * 128 + (uint32_t)ch * 16);
            const size_t gb = bBase + (size_t)r * K + k0 + ch * 8;
            cp_async16(st + 2 * AB_BYTES + so, Bh + gb);
            cp_async16(st + 2 * AB_BYTES + BB_BYTES + so, Bl + gb);
        }
        asm volatile("cp.async.commit_group;" ::: "memory");
    };

    float acc[4][4][4];
#pragma unroll
    for (int i = 0; i < 4; i++)
#pragma unroll
        for (int j = 0; j < 4; j++)
#pragma unroll
            for (int t = 0; t < 4; t++) acc[i][j][t] = 0.0f;

    // ldmatrix lane address components
    const uint32_t arow  = (uint32_t)(warpM * 64 + (lane & 15));
    const uint32_t acolL = (uint32_t)((lane >> 4) * 16);
    const uint32_t brow  = (uint32_t)(warpN * 32 + (lane & 7) + ((lane >> 4) << 3));
    const uint32_t bcolL = (uint32_t)(((lane >> 3) & 1) * 16);

    // double-buffered fragments (R9)
    uint32_t ah[2][4][4], al[2][4][4], bh[2][4][2], bl[2][4][2];

    auto load_frags = [&](uint32_t sA0, uint32_t sA1, uint32_t sB0, uint32_t sB1,
                          int ks, int buf) {
        const uint32_t kb = (uint32_t)ks * 32;
#pragma unroll
        for (int ma = 0; ma < 4; ma++) {
            const uint32_t off = sw128((arow + ma * 16) * 128 + kb + acolL);
            ldsm_x4(ah[buf][ma], sA0 + off);
            ldsm_x4(al[buf][ma], sA1 + off);
        }
#pragma unroll
        for (int g = 0; g < 2; g++) {
            const uint32_t off = sw128((brow + g * 16) * 128 + kb + bcolL);
            uint32_t t0[4], t1[4];
            ldsm_x4(t0, sB0 + off);
            ldsm_x4(t1, sB1 + off);
            bh[buf][2 * g][0] = t0[0]; bh[buf][2 * g][1] = t0[1];
            bh[buf][2 * g + 1][0] = t0[2]; bh[buf][2 * g + 1][1] = t0[3];
            bl[buf][2 * g][0] = t1[0]; bl[buf][2 * g][1] = t1[1];
            bl[buf][2 * g + 1][0] = t1[2]; bl[buf][2 * g + 1][1] = t1[3];
        }
    };

    issue_chunk(0);

    for (int c = 0; c < nch; c++) {
        if (c + 1 < nch) {
            issue_chunk(c + 1);
            asm volatile("cp.async.wait_group 1;" ::: "memory");
        } else {
            asm volatile("cp.async.wait_group 0;" ::: "memory");
        }
        __syncthreads();

        const uint32_t st  = sb + (uint32_t)(c & 1) * STG_BYTES;
        const uint32_t sA0 = st;
        const uint32_t sA1 = st + AB_BYTES;
        const uint32_t sB0 = st + 2 * AB_BYTES;
        const uint32_t sB1 = st + 2 * AB_BYTES + BB_BYTES;

        load_frags(sA0, sA1, sB0, sB1, 0, 0);

#pragma unroll
        for (int ks = 0; ks < 4; ks++) {
            const int cur = ks & 1;
            if (ks + 1 < 4) load_frags(sA0, sA1, sB0, sB1, ks + 1, cur ^ 1);
#pragma unroll
            for (int ma = 0; ma < 4; ma++)
#pragma unroll
                for (int na = 0; na < 4; na++) {
                    mma_16816(acc[ma][na], ah[cur][ma], bh[cur][na]);
                    mma_16816(acc[ma][na], ah[cur][ma], bl[cur][na]);
                    mma_16816(acc[ma][na], al[cur][ma], bh[cur][na]);
                }
        }
        __syncthreads();
    }

    // ---- epilogue: bias + store; q tiles fp32, k/v tiles fp16 ----
    const int bx = blockIdx.x;
    const int row0 = blockIdx.y * 128 + warpM * 64 + (lane >> 2);
    const int lcol = warpN * 32 + (lane & 3) * 2;       // col within 64-wide tile
#pragma unroll
    for (int na = 0; na < 4; na++) {
        const int wc = lcol + na * 8;
        const int gcol = bx * 64 + wc;                  // col in full N (bias)
        const float2 b2 = *(const float2*)&bias[gcol];
        if (bx < nq) {
#pragma unroll
            for (int ma = 0; ma < 4; ma++) {
                const int r = row0 + ma * 16;
                float2 o0, o1;
                o0.x = acc[ma][na][0] + b2.x;
                o0.y = acc[ma][na][1] + b2.y;
                o1.x = acc[ma][na][2] + b2.x;
                o1.y = acc[ma][na][3] + b2.y;
                *(float2*)&Cq[(size_t)r * 256 + gcol]       = o0;
                *(float2*)&Cq[(size_t)(r + 8) * 256 + gcol] = o1;
            }
        } else {
            const int kvc = (bx - nq) * 64 + wc;        // col in 512-wide kv
#pragma unroll
            for (int ma = 0; ma < 4; ma++) {
                const int r = row0 + ma * 16;
                __half2 o0 = __floats2half2_rn(acc[ma][na][0] + b2.x,
                                               acc[ma][na][1] + b2.y);
                __half2 o1 = __floats2half2_rn(acc[ma][na][2] + b2.x,
                                               acc[ma][na][3] + b2.y);
                *(__half2*)&Ckv[(size_t)r * 512 + kvc]       = o0;
                *(__half2*)&Ckv[(size_t)(r + 8) * 512 + kvc] = o1;
            }
        }
    }
}

// ---------------------------------------------------------------------------
// 2D neighborhood attention (7x7), one block = 8x8 pixel tile x 1 head.
// q from fp32 buffer; k/v already fp16 in g_kv -> straight copy to smem.
// 8 lanes per pixel (lane owns 4 dims). Transpose-reduce scores; exp once
// per neighbor; width-8 shfl rebroadcast in pass 2.
// ---------------------------------------------------------------------------
__global__ __launch_bounds__(256, 1)
void na_attn(const float* __restrict__ qbuf, const __half* __restrict__ kvbuf,
             __nv_bfloat16* __restrict__ outh, __nv_bfloat16* __restrict__ outl)
{
    extern __shared__ h2x2 smn[];

    const int c0   = blockIdx.x * 8;
    const int r0   = blockIdx.y * 8;
    const int head = blockIdx.z;

    const int rlo = max(r0 - 3, 0);
    const int rhi = min(r0 + 10, HH - 1);
    const int nr  = rhi - rlo + 1;
    const int clo = max(c0 - 3, 0);
    const int chi = min(c0 + 10, WW - 1);
    const int nc  = chi - clo + 1;
    const int npx = nr * nc;

    h2x2* sK = smn;                    // npx * 8 h2x2 (32 halves per pixel)
    h2x2* sV = smn + npx * 8;

    const int tid = threadIdx.x;

    // Straight copy of fp16 k/v window into smem (no conversion)
    for (int t = tid; t < npx * (HD / 4); t += 256) {
        int p = t >> 3;
        int f = t & 7;
        int gy = rlo + p / nc;
        int gx = clo + p % nc;
        const __half* base = kvbuf + (size_t)(gy * WW + gx) * 512 + head * HD;
        sK[p * 8 + f] = *(const h2x2*)(base + f * 4);
        sV[p * 8 + f] = *(const h2x2*)(base + 256 + f * 4);
    }
    __syncthreads();

    const int warp = tid >> 5;
    const int lane = tid & 31;
    const int sub  = lane >> 3;
    const int l8   = lane & 7;
    const int gy   = r0 + warp;
    const float scale = 0.17677669529663687f;   // 1/sqrt(32)

    const int sy = min(max(gy - 3, 0), HH - KK) - rlo;

#pragma unroll
    for (int t = 0; t < 2; t++) {
        const int gx = c0 + t * 4 + sub;
        const size_t pix = (size_t)(gy * WW + gx);

        float4 q4 = *(const float4*)&qbuf[pix * CC + head * HD + l8 * 4];
        q4.x *= scale; q4.y *= scale; q4.z *= scale; q4.w *= scale;

        const int sx = min(max(gx - 3, 0), WW - KK) - clo;
        const int base = (sy * nc + sx) * 8 + l8;   // h2x2 index

        // ---- pass 1: scores. 6 groups of 8 + neighbor 48 ----
        float own[6];      // lane owns score of neighbor g*8 + l8
#pragma unroll
        for (int g = 0; g < 6; g++) {
            float r[8];
#pragma unroll
            for (int j = 0; j < 8; j++) {
                const int idx = g * 8 + j;
                const int p = idx / KK, q = idx % KK;
                const h2x2 kp = sK[base + (p * nc + q) * 8];
                const float2 k01 = __half22float2(kp.a);
                const float2 k23 = __half22float2(kp.b);
                float s = q4.x * k01.x;
                s = fmaf(q4.y, k01.y, s);
                s = fmaf(q4.z, k23.x, s);
                s = fmaf(q4.w, k23.y, s);
                r[j] = s;
            }
            // 8x8 transpose-reduce: 7 shfl; lane l8 ends with neighbor g*8+l8
#pragma unroll
            for (int j = 0; j < 4; j++) {
                float snd = (l8 & 4) ? r[j] : r[j + 4];
                float rcv = __shfl_xor_sync(0xffffffffu, snd, 4);
                r[j] = ((l8 & 4) ? r[j + 4] : r[j]) + rcv;
            }
#pragma unroll
            for (int j = 0; j < 2; j++) {
                float snd = (l8 & 2) ? r[j] : r[j + 2];
                float rcv = __shfl_xor_sync(0xffffffffu, snd, 2);
                r[j] = ((l8 & 2) ? r[j + 2] : r[j]) + rcv;
            }
            {
                float snd = (l8 & 1) ? r[0] : r[1];
                float rcv = __shfl_xor_sync(0xffffffffu, snd, 1);
                r[0] = ((l8 & 1) ? r[1] : r[0]) + rcv;
            }
            own[g] = r[0];
        }
        // neighbor 48 (p=6,q=6): classic butterfly, all lanes get it
        float s48;
        {
            const h2x2 kp = sK[base + (6 * nc + 6) * 8];
            const float2 k01 = __half22float2(kp.a);
            const float2 k23 = __half22float2(kp.b);
            float s = q4.x * k01.x;
            s = fmaf(q4.y, k01.y, s);
            s = fmaf(q4.z, k23.x, s);
            s = fmaf(q4.w, k23.y, s);
            s += __shfl_xor_sync(0xffffffffu, s, 4);
            s += __shfl_xor_sync(0xffffffffu, s, 2);
            s += __shfl_xor_sync(0xffffffffu, s, 1);
            s48 = s;
        }

        // ---- max (distributed + butterfly) ----
        float m = s48;
#pragma unroll
        for (int g = 0; g < 6; g++) m = fmaxf(m, own[g]);
        m = fmaxf(m, __shfl_xor_sync(0xffffffffu, m, 4));
        m = fmaxf(m, __shfl_xor_sync(0xffffffffu, m, 2));
        m = fmaxf(m, __shfl_xor_sync(0xffffffffu, m, 1));

        // ---- exp (once per neighbor) + sum ----
        float e[6];
        float esum = 0.0f;
#pragma unroll
        for (int g = 0; g < 6; g++) {
            e[g] = __expf(own[g] - m);
            esum += e[g];
        }
        esum += __shfl_xor_sync(0xffffffffu, esum, 4);
        esum += __shfl_xor_sync(0xffffffffu, esum, 2);
        esum += __shfl_xor_sync(0xffffffffu, esum, 1);
        const float e48 = __expf(s48 - m);
        const float l = esum + e48;

        // ---- pass 2: weighted V accumulation ----
        float4 acc = make_float4(0.f, 0.f, 0.f, 0.f);
#pragma unroll
        for (int g = 0; g < 6; g++) {
#pragma unroll
            for (int j = 0; j < 8; j++) {
                const float eb = __shfl_sync(0xffffffffu, e[g], j, 8);
                const int idx = g * 8 + j;
                const int p = idx / KK, q = idx % KK;
                const h2x2 vp = sV[base + (p * nc + q) * 8];
                const float2 v01 = __half22float2(vp.a);
                const float2 v23 = __half22float2(vp.b);
                acc.x = fmaf(eb, v01.x, acc.x);
                acc.y = fmaf(eb, v01.y, acc.y);
                acc.z = fmaf(eb, v23.x, acc.z);
                acc.w = fmaf(eb, v23.y, acc.w);
            }
        }
        {
            const h2x2 vp = sV[base + (6 * nc + 6) * 8];
            const float2 v01 = __half22float2(vp.a);
            const float2 v23 = __half22float2(vp.b);
            acc.x = fmaf(e48, v01.x, acc.x);
            acc.y = fmaf(e48, v01.y, acc.y);
            acc.z = fmaf(e48, v23.x, acc.z);
            acc.w = fmaf(e48, v23.y, acc.w);
        }

        const float inv = 1.0f / l;
        float vals[4] = {acc.x * inv, acc.y * inv, acc.z * inv, acc.w * inv};
        const size_t idx = pix * CC + head * HD + l8 * 4;
#pragma unroll
        for (int j = 0; j < 4; j++) {
            __nv_bfloat16 hi = __float2bfloat16(vals[j]);
            outh[idx + j] = hi;
            outl[idx + j] = __float2bfloat16(vals[j] - __bfloat162float(hi));
        }
    }
}

// ---------------------------------------------------------------------------
// kernel_launch
// ---------------------------------------------------------------------------
extern "C" void kernel_launch(void* const* d_in, const int* in_sizes, int n_in,
                              void* d_out, int out_size)
{
    const float* x      = (const float*)d_in[0];
    const float* w_qkv  = (const float*)d_in[1];
    const float* b_qkv  = (const float*)d_in[2];
    const float* w_proj = (const float*)d_in[3];
    const float* b_proj = (const float*)d_in[4];
    float* out = (float*)d_out;

    float *qb;
    __half *kvb;
    __nv_bfloat16 *xh, *xl, *wqh, *wql, *wph, *wpl, *ath, *atl;
    cudaGetSymbolAddress((void**)&qb,  g_q);
    cudaGetSymbolAddress((void**)&kvb, g_kv);
    cudaGetSymbolAddress((void**)&xh,  g_xh);
    cudaGetSymbolAddress((void**)&xl,  g_xl);
    cudaGetSymbolAddress((void**)&wqh, g_wqkvT_h);
    cudaGetSymbolAddress((void**)&wql, g_wqkvT_l);
    cudaGetSymbolAddress((void**)&wph, g_wprojT_h);
    cudaGetSymbolAddress((void**)&wpl, g_wprojT_l);
    cudaGetSymbolAddress((void**)&ath, g_atth);
    cudaGetSymbolAddress((void**)&atl, g_attl);

    cudaFuncSetAttribute(gemm_mma, cudaFuncAttributeMaxDynamicSharedMemorySize,
                         GT_SMEM);

    // 0) Fused prep: split x (vectorized) + transpose/split both weights
    prep_all<<<PREP_XB + PREP_QB + PREP_PB, 256>>>(x, w_qkv, w_proj,
                                                   xh, xl, wqh, wql, wph, wpl);

    // 1) QKV projection: [8192,256] @ [256,768] + b
    //    64-col tiles 0-3 -> q fp32; tiles 4-11 -> k|v fp16 into kv buffer
    {
        dim3 grid(C3 / 64, NPIX / 128);
        gemm_mma<<<grid, 128, GT_SMEM>>>(xh, xl, wqh, wql, b_qkv,
                                         qb, kvb, /*nq=*/4, CC);
    }

    // 2) Neighborhood attention (fp16 k/v direct; emits bf16 hi/lo)
    {
        const int smem = 2 * 14 * 14 * 8 * (int)sizeof(h2x2);  // 25088 B
        dim3 grid(WW / 8, HH / 8, NH);
        na_attn<<<grid, 256, smem>>>(qb, kvb, ath, atl);
    }

    // 3) Output projection: [8192,256] @ [256,256] + b (all fp32 tiles)
    {
        dim3 grid(CC / 64, NPIX / 128);
        gemm_mma<<<grid, 128, GT_SMEM>>>(ath, atl, wph, wpl, b_proj,
                                         out, (__half*)nullptr, /*nq=*/4, CC);
    }
}